// round 14
// baseline (speedup 1.0000x reference)
#include <cuda_runtime.h>
#include <cuda_bf16.h>
#include <cstdint>

#define N_NODES 100000
#define DIM     128
#define ALPHA_C 0.1f
#define BETA_C  0.4054651081081644f   // ln(1.5)
#define EMAX    3200000
#define SCAN_B  1024
#define NB_SCAN ((N_NODES + SCAN_B - 1) / SCAN_B)   // 98
#define NHALF   50048                               // 391 * 128

// Padded bf16 tile layout: row stride 136 elements (272 bytes, 16B-aligned,
// conflict-free for ldmatrix)
#define TSTRIDE 136
#define TILE_ELEMS (DIM * TSTRIDE)          // 17408 bf16 per image
#define TILE_BYTES (TILE_ELEMS * 2)         // 34816 B

// ---------------------------------------------------------------------------
// Device scratch (allocation is forbidden)
// ---------------------------------------------------------------------------
__device__ __align__(256) float g_side[(size_t)N_NODES * DIM];
__device__ __align__(256) __nv_bfloat16 g_egobf[(size_t)N_NODES * DIM];
__device__ __align__(256) int   g_cnt[N_NODES];
__device__ __align__(256) int   g_start[N_NODES];    // block-local exclusive
__device__ __align__(256) int   g_cursor[N_NODES];   // block-local cursor
__device__ __align__(256) int   g_bsum[SCAN_B];
__device__ __align__(256) int   g_boff[SCAN_B];
__device__ __align__(256) int2  g_edge[EMAX];    // interleaved (col, val-bits)
// Packed B images: [0]=B1h [1]=B1l [2]=B2h [3]=B2l, each [n][k] stride TSTRIDE
__device__ __align__(256) __nv_bfloat16 g_Bpack[4 * TILE_ELEMS];

// ---------------------------------------------------------------------------
// Host-side streams/events, created once at static-init (host objects).
// ---------------------------------------------------------------------------
struct HxStreams {
    cudaStream_t s2 = nullptr;
    cudaEvent_t evStart = nullptr, evE = nullptr, evFork = nullptr, evJoin = nullptr;
    bool ok = false;
    HxStreams() {
        if (cudaStreamCreateWithFlags(&s2, cudaStreamNonBlocking) != cudaSuccess) return;
        if (cudaEventCreateWithFlags(&evStart, cudaEventDisableTiming) != cudaSuccess) return;
        if (cudaEventCreateWithFlags(&evE,     cudaEventDisableTiming) != cudaSuccess) return;
        if (cudaEventCreateWithFlags(&evFork,  cudaEventDisableTiming) != cudaSuccess) return;
        if (cudaEventCreateWithFlags(&evJoin,  cudaEventDisableTiming) != cudaSuccess) return;
        ok = true;
    }
};
static HxStreams g_hx;

// ---------------------------------------------------------------------------
// bit-cast helpers (bf16x2 <-> uint32)
// ---------------------------------------------------------------------------
__device__ __forceinline__ uint32_t bf2_to_u32(__nv_bfloat162 v) {
    __nv_bfloat162_raw r = v;
    return (uint32_t)r.x | ((uint32_t)r.y << 16);
}
__device__ __forceinline__ float2 u32_to_f2(uint32_t u) {
    __nv_bfloat162_raw r;
    r.x = (unsigned short)(u & 0xFFFFu);
    r.y = (unsigned short)(u >> 16);
    return __bfloat1622float2(__nv_bfloat162(r));
}

// ---------------------------------------------------------------------------
// PTX helpers: ldmatrix + bf16 mma (target-portable on compute_103)
// ---------------------------------------------------------------------------
__device__ __forceinline__ uint32_t smem_u32(const void* p) {
    uint32_t a;
    asm("{ .reg .u64 t; cvta.to.shared.u64 t, %1; cvt.u32.u64 %0, t; }" : "=r"(a) : "l"(p));
    return a;
}
__device__ __forceinline__ void ldmat_x4(uint32_t* r, uint32_t addr) {
    asm volatile("ldmatrix.sync.aligned.m8n8.x4.shared.b16 {%0,%1,%2,%3}, [%4];"
                 : "=r"(r[0]), "=r"(r[1]), "=r"(r[2]), "=r"(r[3]) : "r"(addr));
}
__device__ __forceinline__ void mma_bf16(float* d, const uint32_t* a, const uint32_t* b) {
    asm volatile(
        "mma.sync.aligned.m16n8k16.row.col.f32.bf16.bf16.f32 "
        "{%0,%1,%2,%3},{%4,%5,%6,%7},{%8,%9},{%0,%1,%2,%3};"
        : "+f"(d[0]), "+f"(d[1]), "+f"(d[2]), "+f"(d[3])
        : "r"(a[0]), "r"(a[1]), "r"(a[2]), "r"(a[3]), "r"(b[0]), "r"(b[1]));
}

__device__ __forceinline__ float lrelu(float x) { return fmaxf(x, 0.01f * x); }

// ---------------------------------------------------------------------------
// compute_M: M1 = im@w1, M2 = im@w2 (im = (1-beta)+beta*weight); store
// transposed hi/lo bf16 into padded [n][k] images.
// ---------------------------------------------------------------------------
__global__ void compute_M_kernel(const float* __restrict__ weight,
                                 const float* __restrict__ w1,
                                 const float* __restrict__ w2) {
    __shared__ float sIm[DIM];
    const int i = blockIdx.x;   // k
    const int j = threadIdx.x;  // n
    sIm[j] = (1.0f - BETA_C) + BETA_C * weight[i * DIM + j];
    __syncthreads();
    float a1 = 0.0f, a2 = 0.0f;
#pragma unroll 8
    for (int k = 0; k < DIM; k++) {
        const float im = sIm[k];
        a1 = fmaf(im, __ldg(w1 + k * DIM + j), a1);
        a2 = fmaf(im, __ldg(w2 + k * DIM + j), a2);
    }
    const __nv_bfloat16 h1 = __float2bfloat16(a1);
    const __nv_bfloat16 l1 = __float2bfloat16(a1 - __bfloat162float(h1));
    const __nv_bfloat16 h2 = __float2bfloat16(a2);
    const __nv_bfloat16 l2 = __float2bfloat16(a2 - __bfloat162float(h2));
    const int base = j * TSTRIDE + i;    // [n][k]
    g_Bpack[0 * TILE_ELEMS + base] = h1;
    g_Bpack[1 * TILE_ELEMS + base] = l1;
    g_Bpack[2 * TILE_ELEMS + base] = h2;
    g_Bpack[3 * TILE_ELEMS + base] = l2;
}

// ---------------------------------------------------------------------------
// ego -> bf16 copy
// ---------------------------------------------------------------------------
__global__ void ego_bf16_kernel(const float* __restrict__ ego) {
    const int idx = blockIdx.x * blockDim.x + threadIdx.x;   // one per 8 elems
    const int total = N_NODES * DIM / 8;
    if (idx >= total) return;
    const float4 a = __ldg(reinterpret_cast<const float4*>(ego) + idx * 2);
    const float4 b = __ldg(reinterpret_cast<const float4*>(ego) + idx * 2 + 1);
    uint4 o;
    o.x = bf2_to_u32(__floats2bfloat162_rn(a.x, a.y));
    o.y = bf2_to_u32(__floats2bfloat162_rn(a.z, a.w));
    o.z = bf2_to_u32(__floats2bfloat162_rn(b.x, b.y));
    o.w = bf2_to_u32(__floats2bfloat162_rn(b.z, b.w));
    reinterpret_cast<uint4*>(g_egobf)[idx] = o;
}

// ---------------------------------------------------------------------------
// CSR build: zero -> hist -> scan1 (writes local excl) -> scan2 (block offsets)
// -> scatter (adds boff on the fly). No scan3.
// ---------------------------------------------------------------------------
__global__ void zero_cnt_kernel() {
    const int i = blockIdx.x * blockDim.x + threadIdx.x;
    if (i < N_NODES) g_cnt[i] = 0;
}
__global__ void hist_kernel(const int* __restrict__ row, int E) {
    const int tid = blockIdx.x * blockDim.x + threadIdx.x;
    const int stride = gridDim.x * blockDim.x;
    const int n4 = E >> 2;
    for (int i = tid; i < n4; i += stride) {
        const int4 r = __ldg(reinterpret_cast<const int4*>(row) + i);
        atomicAdd(&g_cnt[r.x], 1);
        atomicAdd(&g_cnt[r.y], 1);
        atomicAdd(&g_cnt[r.z], 1);
        atomicAdd(&g_cnt[r.w], 1);
    }
    if (tid < (E & 3)) atomicAdd(&g_cnt[__ldg(row + (n4 << 2) + tid)], 1);
}
__global__ void scan1_kernel() {
    __shared__ int s[SCAN_B];
    const int tid = threadIdx.x;
    const int i = blockIdx.x * SCAN_B + tid;
    int v = (i < N_NODES) ? g_cnt[i] : 0;
    s[tid] = v;
    __syncthreads();
#pragma unroll
    for (int off = 1; off < SCAN_B; off <<= 1) {
        int t = (tid >= off) ? s[tid - off] : 0;
        __syncthreads();
        s[tid] += t;
        __syncthreads();
    }
    if (i < N_NODES) {
        const int excl = s[tid] - v;     // block-local exclusive
        g_start[i]  = excl;
        g_cursor[i] = excl;
    }
    if (tid == SCAN_B - 1) g_bsum[blockIdx.x] = s[tid];
}
__global__ void scan2_kernel() {
    __shared__ int s[128];
    const int tid = threadIdx.x;
    int v = (tid < NB_SCAN) ? g_bsum[tid] : 0;
    s[tid] = v;
    __syncthreads();
#pragma unroll
    for (int off = 1; off < 128; off <<= 1) {
        int t = (tid >= off) ? s[tid - off] : 0;
        __syncthreads();
        s[tid] += t;
        __syncthreads();
    }
    if (tid < NB_SCAN) g_boff[tid] = s[tid] - v;
}
__global__ void scatter_kernel(const int* __restrict__ row,
                               const int* __restrict__ col,
                               const float* __restrict__ vals, int E) {
    const int tid = blockIdx.x * blockDim.x + threadIdx.x;
    const int stride = gridDim.x * blockDim.x;
    const int n4 = E >> 2;
    for (int i = tid; i < n4; i += stride) {
        const int4   r = __ldg(reinterpret_cast<const int4*>(row) + i);
        const int4   c = __ldg(reinterpret_cast<const int4*>(col) + i);
        const float4 v = __ldg(reinterpret_cast<const float4*>(vals) + i);
        int p0 = atomicAdd(&g_cursor[r.x], 1) + __ldg(g_boff + (r.x >> 10));
        int p1 = atomicAdd(&g_cursor[r.y], 1) + __ldg(g_boff + (r.y >> 10));
        int p2 = atomicAdd(&g_cursor[r.z], 1) + __ldg(g_boff + (r.z >> 10));
        int p3 = atomicAdd(&g_cursor[r.w], 1) + __ldg(g_boff + (r.w >> 10));
        g_edge[p0] = make_int2(c.x, __float_as_int(v.x));
        g_edge[p1] = make_int2(c.y, __float_as_int(v.y));
        g_edge[p2] = make_int2(c.z, __float_as_int(v.z));
        g_edge[p3] = make_int2(c.w, __float_as_int(v.w));
    }
    if (tid < (E & 3)) {
        const int e = (n4 << 2) + tid;
        const int r = __ldg(row + e);
        const int pos = atomicAdd(&g_cursor[r], 1) + __ldg(g_boff + (r >> 10));
        g_edge[pos] = make_int2(__ldg(col + e), __float_as_int(__ldg(vals + e)));
    }
}

// ---------------------------------------------------------------------------
// Gather SpMM: one warp per row, bf16 ego gather, interleaved edge loads.
// Row range [base, limit).
// ---------------------------------------------------------------------------
__device__ __forceinline__ void acc_edge(float4& acc, float v, uint2 p) {
    const float2 f0 = u32_to_f2(p.x);
    const float2 f1 = u32_to_f2(p.y);
    acc.x = fmaf(v, f0.x, acc.x);
    acc.y = fmaf(v, f0.y, acc.y);
    acc.z = fmaf(v, f1.x, acc.z);
    acc.w = fmaf(v, f1.y, acc.w);
}

__global__ __launch_bounds__(256)
void gather_spmm_kernel(int base, int limit) {
    const int wid  = base + ((blockIdx.x * blockDim.x + threadIdx.x) >> 5);
    const int lane = threadIdx.x & 31;
    if (wid >= limit) return;

    const int start = g_start[wid] + __ldg(g_boff + (wid >> 10));
    const int cnt   = g_cnt[wid];

    float4 acc = make_float4(0.f, 0.f, 0.f, 0.f);

    for (int j0 = 0; j0 < cnt; j0 += 32) {
        const int rem = min(32, cnt - j0);
        int   myc = 0;
        float myv = 0.f;
        if (lane < rem) {
            const int2 ed = __ldg(g_edge + start + j0 + lane);
            myc = ed.x;
            myv = __int_as_float(ed.y);
        }
        int kk = 0;
        for (; kk + 8 <= rem; kk += 8) {
            int   c[8];
            float v[8];
            uint2 p[8];
#pragma unroll
            for (int q = 0; q < 8; q++) {
                c[q] = __shfl_sync(0xffffffffu, myc, kk + q);
                v[q] = __shfl_sync(0xffffffffu, myv, kk + q);
            }
#pragma unroll
            for (int q = 0; q < 8; q++)
                p[q] = __ldg(reinterpret_cast<const uint2*>(g_egobf + (size_t)c[q] * DIM) + lane);
#pragma unroll
            for (int q = 0; q < 8; q++) acc_edge(acc, v[q], p[q]);
        }
        for (; kk < rem; kk++) {
            const int   c = __shfl_sync(0xffffffffu, myc, kk);
            const float v = __shfl_sync(0xffffffffu, myv, kk);
            const uint2 p = __ldg(reinterpret_cast<const uint2*>(g_egobf + (size_t)c * DIM) + lane);
            acc_edge(acc, v, p);
        }
    }
    reinterpret_cast<float4*>(g_side + (size_t)wid * DIM)[lane] = acc;
}

// ---------------------------------------------------------------------------
// Fused dense via mma.sync (bf16x3 split == ~fp32), 512 threads / CTA.
// Single-pass X build; B1 then B2 swapped through one smem slot.
// ---------------------------------------------------------------------------
#define FM_THREADS 512

extern __shared__ __nv_bfloat16 fm_smem[];

__device__ __forceinline__ void split_store(__nv_bfloat16* sH, __nv_bfloat16* sL,
                                            int idx, const float* v) {
#pragma unroll
    for (int j = 0; j < 2; j++) {
        const __nv_bfloat16 h0b = __float2bfloat16(v[j * 2 + 0]);
        const __nv_bfloat16 h1b = __float2bfloat16(v[j * 2 + 1]);
        *reinterpret_cast<__nv_bfloat162*>(sH + idx + j * 2) = __halves2bfloat162(h0b, h1b);
        *reinterpret_cast<__nv_bfloat162*>(sL + idx + j * 2) =
            __halves2bfloat162(__float2bfloat16(v[j * 2 + 0] - __bfloat162float(h0b)),
                               __float2bfloat16(v[j * 2 + 1] - __bfloat162float(h1b)));
    }
}

__device__ __forceinline__ void build_x_both(__nv_bfloat16* sA1h, __nv_bfloat16* sA1l,
                                             __nv_bfloat16* sA2h, __nv_bfloat16* sA2l,
                                             const float* __restrict__ ego,
                                             const float* __restrict__ h0,
                                             int row0, int tid) {
#pragma unroll
    for (int i = tid; i < 128 * 32; i += FM_THREADS) {
        const int r  = i >> 5;
        const int c4 = i & 31;
        const int grow = row0 + r;
        float v1[4] = {0.f, 0.f, 0.f, 0.f};
        float v2[4] = {0.f, 0.f, 0.f, 0.f};
        if (grow < N_NODES) {
            const float4 e = __ldg(reinterpret_cast<const float4*>(ego + (size_t)grow * DIM) + c4);
            const float4 s = *(reinterpret_cast<const float4*>(g_side + (size_t)grow * DIM) + c4);
            const float4 h = __ldg(reinterpret_cast<const float4*>(h0 + (size_t)grow * DIM) + c4);
            const float oa = 1.0f - ALPHA_C;
            v1[0] = oa * (e.x + s.x) + ALPHA_C * h.x;
            v1[1] = oa * (e.y + s.y) + ALPHA_C * h.y;
            v1[2] = oa * (e.z + s.z) + ALPHA_C * h.z;
            v1[3] = oa * (e.w + s.w) + ALPHA_C * h.w;
            v2[0] = oa * (e.x * s.x) + ALPHA_C * h.x;
            v2[1] = oa * (e.y * s.y) + ALPHA_C * h.y;
            v2[2] = oa * (e.z * s.z) + ALPHA_C * h.z;
            v2[3] = oa * (e.w * s.w) + ALPHA_C * h.w;
        }
        const int idx = r * TSTRIDE + c4 * 4;
        split_store(sA1h, sA1l, idx, v1);
        split_store(sA2h, sA2l, idx, v2);
    }
}

__device__ __forceinline__ void run_branch(uint32_t aH, uint32_t aL,
                                           uint32_t bH, uint32_t bL,
                                           float* acc) {
#pragma unroll
    for (int i = 0; i < 32; i++) acc[i] = 0.f;
    for (int ks = 0; ks < 8; ks++) {
        const uint32_t ko = (uint32_t)ks * 32;   // 16 k-elems * 2B
        uint32_t ah[4], al[4];
        ldmat_x4(ah, aH + ko);
        ldmat_x4(al, aL + ko);
#pragma unroll
        for (int np = 0; np < 4; np++) {
            uint32_t bh[4], bl[4];
            const uint32_t bo = (uint32_t)np * (16 * TSTRIDE * 2) + ko;
            ldmat_x4(bh, bH + bo);
            ldmat_x4(bl, bL + bo);
            float* a0 = acc + np * 8;
            mma_bf16(a0,     ah, bh);
            mma_bf16(a0 + 4, ah, bh + 2);
            mma_bf16(a0,     al, bh);
            mma_bf16(a0 + 4, al, bh + 2);
            mma_bf16(a0,     ah, bl);
            mma_bf16(a0 + 4, ah, bl + 2);
        }
    }
}

__global__ __launch_bounds__(FM_THREADS, 1)
void fused_mma_kernel(int row_base,
                      const float* __restrict__ ego,
                      const float* __restrict__ h0,
                      const float* __restrict__ b1,
                      const float* __restrict__ b2,
                      float* __restrict__ out) {
    __shared__ float sb1[DIM], sb2[DIM];

    __nv_bfloat16* sA1h = fm_smem;
    __nv_bfloat16* sA1l = sA1h + TILE_ELEMS;
    __nv_bfloat16* sA2h = sA1l + TILE_ELEMS;
    __nv_bfloat16* sA2l = sA2h + TILE_ELEMS;
    __nv_bfloat16* sBh  = sA2l + TILE_ELEMS;   // one B pair (hi,lo contiguous)

    const int tid  = threadIdx.x;
    const int lane = tid & 31;
    const int w    = tid >> 5;          // 0..15
    const int wr   = w & 7;             // row-group (16 rows)
    const int wn   = w >> 3;            // n-half (64 cols)
    const int row0 = row_base + blockIdx.x * 128;

    if (tid < DIM) { sb1[tid] = b1[tid]; sb2[tid] = b2[tid]; }

    // Copy B1 pair (images 0,1)
    {
        const uint4* g = reinterpret_cast<const uint4*>(g_Bpack);
        uint4* d = reinterpret_cast<uint4*>(sBh);
#pragma unroll
        for (int i = tid; i < 2 * TILE_BYTES / 16; i += FM_THREADS) d[i] = __ldg(g + i);
    }

    // Build both X tiles in one pass
    build_x_both(sA1h, sA1l, sA2h, sA2l, ego, h0, row0, tid);
    __syncthreads();

    // Per-thread ldmatrix base addresses
    const uint32_t aRowByte = (uint32_t)((wr * 16 + (lane & 15)) * (TSTRIDE * 2) + ((lane >> 4) & 1) * 16);
    const uint32_t bRowByte = (uint32_t)((wn * 64 + (lane & 7) + ((lane >> 4) << 3)) * (TSTRIDE * 2) + ((lane >> 3) & 1) * 16);
    const uint32_t a1H = smem_u32(sA1h) + aRowByte;
    const uint32_t a1L = a1H + TILE_BYTES;
    const uint32_t a2H = a1H + 2 * TILE_BYTES;
    const uint32_t a2L = a1H + 3 * TILE_BYTES;
    const uint32_t bH  = smem_u32(sBh) + bRowByte;
    const uint32_t bL  = bH + TILE_BYTES;

    float acc[32], r1[32];

    // Branch 1
    run_branch(a1H, a1L, bH, bL, acc);
    {
        const int c0 = wn * 64 + (lane & 3) * 2;
#pragma unroll
        for (int nt = 0; nt < 8; nt++) {
            const int c = nt * 8 + c0;
            const float bb0 = sb1[c], bbv = sb1[c + 1];
            r1[nt * 4 + 0] = lrelu(acc[nt * 4 + 0] + bb0);
            r1[nt * 4 + 1] = lrelu(acc[nt * 4 + 1] + bbv);
            r1[nt * 4 + 2] = lrelu(acc[nt * 4 + 2] + bb0);
            r1[nt * 4 + 3] = lrelu(acc[nt * 4 + 3] + bbv);
        }
    }
    __syncthreads();               // all warps done reading B1

    // Swap in B2 pair (images 2,3)
    {
        const uint4* g = reinterpret_cast<const uint4*>(g_Bpack) + 2 * TILE_BYTES / 16;
        uint4* d = reinterpret_cast<uint4*>(sBh);
#pragma unroll
        for (int i = tid; i < 2 * TILE_BYTES / 16; i += FM_THREADS) d[i] = __ldg(g + i);
    }
    __syncthreads();

    // Branch 2 (X2 already in smem)
    run_branch(a2H, a2L, bH, bL, acc);

    // Epilogue
    {
        const int c0 = wn * 64 + (lane & 3) * 2;
        const int rlow  = row0 + wr * 16 + (lane >> 2);
        const int rhigh = rlow + 8;
#pragma unroll
        for (int nt = 0; nt < 8; nt++) {
            const int c = nt * 8 + c0;
            const float bb0 = sb2[c], bbv = sb2[c + 1];
            if (rlow < N_NODES) {
                float2 o;
                o.x = r1[nt * 4 + 0] + lrelu(acc[nt * 4 + 0] + bb0);
                o.y = r1[nt * 4 + 1] + lrelu(acc[nt * 4 + 1] + bbv);
                *reinterpret_cast<float2*>(out + (size_t)rlow * DIM + c) = o;
            }
            if (rhigh < N_NODES) {
                float2 o;
                o.x = r1[nt * 4 + 2] + lrelu(acc[nt * 4 + 2] + bb0);
                o.y = r1[nt * 4 + 3] + lrelu(acc[nt * 4 + 3] + bbv);
                *reinterpret_cast<float2*>(out + (size_t)rhigh * DIM + c) = o;
            }
        }
    }
}

// ---------------------------------------------------------------------------
// Launch
// Inputs: 0=ego 1=h0 2=vals 3=weight 4=w1 5=b1 6=w2 7=b2 8=row 9=col
// ---------------------------------------------------------------------------
extern "C" void kernel_launch(void* const* d_in, const int* in_sizes, int n_in,
                              void* d_out, int out_size) {
    const float* ego    = (const float*)d_in[0];
    const float* h0     = (const float*)d_in[1];
    const float* vals   = (const float*)d_in[2];
    const float* weight = (const float*)d_in[3];
    const float* w1     = (const float*)d_in[4];
    const float* b1     = (const float*)d_in[5];
    const float* w2     = (const float*)d_in[6];
    const float* b2     = (const float*)d_in[7];
    const int*   row    = (const int*)d_in[8];
    const int*   col    = (const int*)d_in[9];
    float* out = (float*)d_out;

    const int E = in_sizes[2];
    const int smem_bytes = 6 * TILE_BYTES;   // 208896
    cudaFuncSetAttribute(fused_mma_kernel, cudaFuncAttributeMaxDynamicSharedMemorySize, smem_bytes);

    const bool par = g_hx.ok;
    cudaStream_t s0 = 0;
    cudaStream_t s2 = par ? g_hx.s2 : (cudaStream_t)0;
    const int wpb = 8;

    if (par) {
        cudaEventRecord(g_hx.evStart, s0);
        cudaStreamWaitEvent(s2, g_hx.evStart, 0);
        // side stream: fold weights + ego conversion (both independent of CSR)
        compute_M_kernel<<<DIM, DIM, 0, s2>>>(weight, w1, w2);
        {
            const int total = N_NODES * DIM / 8;
            ego_bf16_kernel<<<(total + 255) / 256, 256, 0, s2>>>(ego);
        }
        cudaEventRecord(g_hx.evE, s2);

        // main stream: CSR chain (no scan3)
        zero_cnt_kernel<<<(N_NODES + 255) / 256, 256, 0, s0>>>();
        hist_kernel<<<1184, 256, 0, s0>>>(row, E);
        scan1_kernel<<<NB_SCAN, SCAN_B, 0, s0>>>();
        scan2_kernel<<<1, 128, 0, s0>>>();
        scatter_kernel<<<1184, 256, 0, s0>>>(row, col, vals, E);
        cudaStreamWaitEvent(s0, g_hx.evE, 0);    // gathers need g_egobf (+Bpack later)
        cudaEventRecord(g_hx.evFork, s0);
        cudaStreamWaitEvent(s2, g_hx.evFork, 0); // s2 needs scatter done

        // chunk A on s0, chunk B on s2 (R12 structure)
        gather_spmm_kernel<<<(NHALF + wpb - 1) / wpb, wpb * 32, 0, s0>>>(0, NHALF);
        gather_spmm_kernel<<<(N_NODES - NHALF + wpb - 1) / wpb, wpb * 32, 0, s2>>>(NHALF, N_NODES);
        fused_mma_kernel<<<NHALF / 128, FM_THREADS, smem_bytes, s0>>>(0, ego, h0, b1, b2, out);
        fused_mma_kernel<<<(N_NODES - NHALF + 127) / 128, FM_THREADS, smem_bytes, s2>>>(NHALF, ego, h0, b1, b2, out);
        cudaEventRecord(g_hx.evJoin, s2);
        cudaStreamWaitEvent(s0, g_hx.evJoin, 0);
    } else {
        compute_M_kernel<<<DIM, DIM>>>(weight, w1, w2);
        {
            const int total = N_NODES * DIM / 8;
            ego_bf16_kernel<<<(total + 255) / 256, 256>>>(ego);
        }
        zero_cnt_kernel<<<(N_NODES + 255) / 256, 256>>>();
        hist_kernel<<<1184, 256>>>(row, E);
        scan1_kernel<<<NB_SCAN, SCAN_B>>>();
        scan2_kernel<<<1, 128>>>();
        scatter_kernel<<<1184, 256>>>(row, col, vals, E);
        gather_spmm_kernel<<<(N_NODES + wpb - 1) / wpb, wpb * 32>>>(0, N_NODES);
        fused_mma_kernel<<<(N_NODES + 127) / 128, FM_THREADS, smem_bytes>>>(0, ego, h0, b1, b2, out);
    }
}

// round 16
// speedup vs baseline: 1.3419x; 1.3419x over previous
#include <cuda_runtime.h>
#include <cuda_bf16.h>
#include <cstdint>

#define N_NODES 100000
#define DIM     128
#define ALPHA_C 0.1f
#define BETA_C  0.4054651081081644f   // ln(1.5)
#define EMAX    3200000
#define SCAN_B  1024
#define NB_SCAN ((N_NODES + SCAN_B - 1) / SCAN_B)   // 98
#define NHALF   50048                               // 391 * 128

// Padded bf16 tile layout: row stride 136 elements (272 bytes, 16B-aligned,
// conflict-free for ldmatrix)
#define TSTRIDE 136
#define TILE_ELEMS (DIM * TSTRIDE)          // 17408 bf16 per image
#define TILE_BYTES (TILE_ELEMS * 2)         // 34816 B

// ---------------------------------------------------------------------------
// Device scratch (allocation is forbidden)
// ---------------------------------------------------------------------------
__device__ __align__(256) __nv_bfloat16 g_sidebf[(size_t)N_NODES * DIM];
__device__ __align__(256) __nv_bfloat16 g_egobf[(size_t)N_NODES * DIM];
__device__ __align__(256) int   g_cnt[N_NODES];
__device__ __align__(256) int   g_scan[N_NODES];
__device__ __align__(256) int   g_start[N_NODES];
__device__ __align__(256) int   g_cursor[N_NODES];
__device__ __align__(256) int   g_bsum[SCAN_B];
__device__ __align__(256) int   g_boff[SCAN_B];
__device__ __align__(256) int2  g_edge[EMAX];    // interleaved (col, val-bits)
// Packed B images: [0]=B1h [1]=B1l [2]=B2h [3]=B2l, each [n][k] stride TSTRIDE
__device__ __align__(256) __nv_bfloat16 g_Bpack[4 * TILE_ELEMS];

// ---------------------------------------------------------------------------
// Host-side streams/events, created once at static-init (host objects).
// ---------------------------------------------------------------------------
struct HxStreams {
    cudaStream_t s2 = nullptr;
    cudaEvent_t evStart = nullptr, evM = nullptr, evFork = nullptr, evJoin = nullptr;
    bool ok = false;
    HxStreams() {
        if (cudaStreamCreateWithFlags(&s2, cudaStreamNonBlocking) != cudaSuccess) return;
        if (cudaEventCreateWithFlags(&evStart, cudaEventDisableTiming) != cudaSuccess) return;
        if (cudaEventCreateWithFlags(&evM,     cudaEventDisableTiming) != cudaSuccess) return;
        if (cudaEventCreateWithFlags(&evFork,  cudaEventDisableTiming) != cudaSuccess) return;
        if (cudaEventCreateWithFlags(&evJoin,  cudaEventDisableTiming) != cudaSuccess) return;
        ok = true;
    }
};
static HxStreams g_hx;

// ---------------------------------------------------------------------------
// bit-cast helpers (bf16x2 <-> uint32)
// ---------------------------------------------------------------------------
__device__ __forceinline__ uint32_t bf2_to_u32(__nv_bfloat162 v) {
    __nv_bfloat162_raw r = v;
    return (uint32_t)r.x | ((uint32_t)r.y << 16);
}
__device__ __forceinline__ float2 u32_to_f2(uint32_t u) {
    __nv_bfloat162_raw r;
    r.x = (unsigned short)(u & 0xFFFFu);
    r.y = (unsigned short)(u >> 16);
    return __bfloat1622float2(__nv_bfloat162(r));
}

// ---------------------------------------------------------------------------
// PTX helpers: ldmatrix + bf16 mma (target-portable on compute_103)
// ---------------------------------------------------------------------------
__device__ __forceinline__ uint32_t smem_u32(const void* p) {
    uint32_t a;
    asm("{ .reg .u64 t; cvta.to.shared.u64 t, %1; cvt.u32.u64 %0, t; }" : "=r"(a) : "l"(p));
    return a;
}
__device__ __forceinline__ void ldmat_x4(uint32_t* r, uint32_t addr) {
    asm volatile("ldmatrix.sync.aligned.m8n8.x4.shared.b16 {%0,%1,%2,%3}, [%4];"
                 : "=r"(r[0]), "=r"(r[1]), "=r"(r[2]), "=r"(r[3]) : "r"(addr));
}
__device__ __forceinline__ void mma_bf16(float* d, const uint32_t* a, const uint32_t* b) {
    asm volatile(
        "mma.sync.aligned.m16n8k16.row.col.f32.bf16.bf16.f32 "
        "{%0,%1,%2,%3},{%4,%5,%6,%7},{%8,%9},{%0,%1,%2,%3};"
        : "+f"(d[0]), "+f"(d[1]), "+f"(d[2]), "+f"(d[3])
        : "r"(a[0]), "r"(a[1]), "r"(a[2]), "r"(a[3]), "r"(b[0]), "r"(b[1]));
}

__device__ __forceinline__ float lrelu(float x) { return fmaxf(x, 0.01f * x); }

// ---------------------------------------------------------------------------
// compute_M: M1 = im@w1, M2 = im@w2 (im = (1-beta)+beta*weight); store
// transposed hi/lo bf16 into padded [n][k] images.
// ---------------------------------------------------------------------------
__global__ void compute_M_kernel(const float* __restrict__ weight,
                                 const float* __restrict__ w1,
                                 const float* __restrict__ w2) {
    __shared__ float sIm[DIM];
    const int i = blockIdx.x;   // k
    const int j = threadIdx.x;  // n
    sIm[j] = (1.0f - BETA_C) + BETA_C * weight[i * DIM + j];
    __syncthreads();
    float a1 = 0.0f, a2 = 0.0f;
#pragma unroll 8
    for (int k = 0; k < DIM; k++) {
        const float im = sIm[k];
        a1 = fmaf(im, __ldg(w1 + k * DIM + j), a1);
        a2 = fmaf(im, __ldg(w2 + k * DIM + j), a2);
    }
    const __nv_bfloat16 h1 = __float2bfloat16(a1);
    const __nv_bfloat16 l1 = __float2bfloat16(a1 - __bfloat162float(h1));
    const __nv_bfloat16 h2 = __float2bfloat16(a2);
    const __nv_bfloat16 l2 = __float2bfloat16(a2 - __bfloat162float(h2));
    const int base = j * TSTRIDE + i;    // [n][k]
    g_Bpack[0 * TILE_ELEMS + base] = h1;
    g_Bpack[1 * TILE_ELEMS + base] = l1;
    g_Bpack[2 * TILE_ELEMS + base] = h2;
    g_Bpack[3 * TILE_ELEMS + base] = l2;
}

// ---------------------------------------------------------------------------
// ego -> bf16 copy + zero counts (fused)   [R12 form]
// ---------------------------------------------------------------------------
__global__ void ego_bf16_kernel(const float* __restrict__ ego) {
    const int idx = blockIdx.x * blockDim.x + threadIdx.x;   // one per 8 elems
    const int total = N_NODES * DIM / 8;
    if (idx < N_NODES) g_cnt[idx] = 0;
    if (idx >= total) return;
    const float4 a = __ldg(reinterpret_cast<const float4*>(ego) + idx * 2);
    const float4 b = __ldg(reinterpret_cast<const float4*>(ego) + idx * 2 + 1);
    uint4 o;
    o.x = bf2_to_u32(__floats2bfloat162_rn(a.x, a.y));
    o.y = bf2_to_u32(__floats2bfloat162_rn(a.z, a.w));
    o.z = bf2_to_u32(__floats2bfloat162_rn(b.x, b.y));
    o.w = bf2_to_u32(__floats2bfloat162_rn(b.z, b.w));
    reinterpret_cast<uint4*>(g_egobf)[idx] = o;
}

// ---------------------------------------------------------------------------
// CSR build (hist/scatter vectorized, grid-stride)  [R12 form, scan3 kept]
// ---------------------------------------------------------------------------
__global__ void hist_kernel(const int* __restrict__ row, int E) {
    const int tid = blockIdx.x * blockDim.x + threadIdx.x;
    const int stride = gridDim.x * blockDim.x;
    const int n4 = E >> 2;
    for (int i = tid; i < n4; i += stride) {
        const int4 r = __ldg(reinterpret_cast<const int4*>(row) + i);
        atomicAdd(&g_cnt[r.x], 1);
        atomicAdd(&g_cnt[r.y], 1);
        atomicAdd(&g_cnt[r.z], 1);
        atomicAdd(&g_cnt[r.w], 1);
    }
    if (tid < (E & 3)) atomicAdd(&g_cnt[__ldg(row + (n4 << 2) + tid)], 1);
}
__global__ void scan1_kernel() {
    __shared__ int s[SCAN_B];
    const int tid = threadIdx.x;
    const int i = blockIdx.x * SCAN_B + tid;
    int v = (i < N_NODES) ? g_cnt[i] : 0;
    s[tid] = v;
    __syncthreads();
#pragma unroll
    for (int off = 1; off < SCAN_B; off <<= 1) {
        int t = (tid >= off) ? s[tid - off] : 0;
        __syncthreads();
        s[tid] += t;
        __syncthreads();
    }
    if (i < N_NODES) g_scan[i] = s[tid];
    if (tid == SCAN_B - 1) g_bsum[blockIdx.x] = s[tid];
}
__global__ void scan2_kernel() {
    __shared__ int s[128];
    const int tid = threadIdx.x;
    int v = (tid < NB_SCAN) ? g_bsum[tid] : 0;
    s[tid] = v;
    __syncthreads();
#pragma unroll
    for (int off = 1; off < 128; off <<= 1) {
        int t = (tid >= off) ? s[tid - off] : 0;
        __syncthreads();
        s[tid] += t;
        __syncthreads();
    }
    if (tid < NB_SCAN) g_boff[tid] = s[tid] - v;
}
__global__ void scan3_kernel() {
    const int i = blockIdx.x * blockDim.x + threadIdx.x;
    if (i < N_NODES) {
        const int excl = g_scan[i] - g_cnt[i] + g_boff[i / SCAN_B];
        g_start[i]  = excl;
        g_cursor[i] = excl;
    }
}
__global__ void scatter_kernel(const int* __restrict__ row,
                               const int* __restrict__ col,
                               const float* __restrict__ vals, int E) {
    const int tid = blockIdx.x * blockDim.x + threadIdx.x;
    const int stride = gridDim.x * blockDim.x;
    const int n4 = E >> 2;
    for (int i = tid; i < n4; i += stride) {
        const int4   r = __ldg(reinterpret_cast<const int4*>(row) + i);
        const int4   c = __ldg(reinterpret_cast<const int4*>(col) + i);
        const float4 v = __ldg(reinterpret_cast<const float4*>(vals) + i);
        int p0 = atomicAdd(&g_cursor[r.x], 1);
        int p1 = atomicAdd(&g_cursor[r.y], 1);
        int p2 = atomicAdd(&g_cursor[r.z], 1);
        int p3 = atomicAdd(&g_cursor[r.w], 1);
        g_edge[p0] = make_int2(c.x, __float_as_int(v.x));
        g_edge[p1] = make_int2(c.y, __float_as_int(v.y));
        g_edge[p2] = make_int2(c.z, __float_as_int(v.z));
        g_edge[p3] = make_int2(c.w, __float_as_int(v.w));
    }
    if (tid < (E & 3)) {
        const int e = (n4 << 2) + tid;
        const int r = __ldg(row + e);
        const int pos = atomicAdd(&g_cursor[r], 1);
        g_edge[pos] = make_int2(__ldg(col + e), __float_as_int(__ldg(vals + e)));
    }
}

// ---------------------------------------------------------------------------
// Gather SpMM: one warp per row, bf16 ego gather, interleaved edge loads.
// Row range [base, limit).  Writes side in bf16 (uint2 per lane).
// ---------------------------------------------------------------------------
__device__ __forceinline__ void acc_edge(float4& acc, float v, uint2 p) {
    const float2 f0 = u32_to_f2(p.x);
    const float2 f1 = u32_to_f2(p.y);
    acc.x = fmaf(v, f0.x, acc.x);
    acc.y = fmaf(v, f0.y, acc.y);
    acc.z = fmaf(v, f1.x, acc.z);
    acc.w = fmaf(v, f1.y, acc.w);
}

__global__ __launch_bounds__(256)
void gather_spmm_kernel(int base, int limit) {
    const int wid  = base + ((blockIdx.x * blockDim.x + threadIdx.x) >> 5);
    const int lane = threadIdx.x & 31;
    if (wid >= limit) return;

    const int start = g_start[wid];
    const int cnt   = g_cnt[wid];

    float4 acc = make_float4(0.f, 0.f, 0.f, 0.f);

    for (int j0 = 0; j0 < cnt; j0 += 32) {
        const int rem = min(32, cnt - j0);
        int   myc = 0;
        float myv = 0.f;
        if (lane < rem) {
            const int2 ed = __ldg(g_edge + start + j0 + lane);
            myc = ed.x;
            myv = __int_as_float(ed.y);
        }
        int kk = 0;
        for (; kk + 8 <= rem; kk += 8) {
            int   c[8];
            float v[8];
            uint2 p[8];
#pragma unroll
            for (int q = 0; q < 8; q++) {
                c[q] = __shfl_sync(0xffffffffu, myc, kk + q);
                v[q] = __shfl_sync(0xffffffffu, myv, kk + q);
            }
#pragma unroll
            for (int q = 0; q < 8; q++)
                p[q] = __ldg(reinterpret_cast<const uint2*>(g_egobf + (size_t)c[q] * DIM) + lane);
#pragma unroll
            for (int q = 0; q < 8; q++) acc_edge(acc, v[q], p[q]);
        }
        for (; kk < rem; kk++) {
            const int   c = __shfl_sync(0xffffffffu, myc, kk);
            const float v = __shfl_sync(0xffffffffu, myv, kk);
            const uint2 p = __ldg(reinterpret_cast<const uint2*>(g_egobf + (size_t)c * DIM) + lane);
            acc_edge(acc, v, p);
        }
    }
    // store side in bf16: lane covers cols [lane*4, lane*4+4)
    uint2 o;
    o.x = bf2_to_u32(__floats2bfloat162_rn(acc.x, acc.y));
    o.y = bf2_to_u32(__floats2bfloat162_rn(acc.z, acc.w));
    reinterpret_cast<uint2*>(g_sidebf + (size_t)wid * DIM)[lane] = o;
}

// ---------------------------------------------------------------------------
// Fused dense via mma.sync (bf16x3 split == ~fp32), 512 threads / CTA.
// Single-pass X build (side read in bf16); B1 then B2 through one smem slot.
// ---------------------------------------------------------------------------
#define FM_THREADS 512

extern __shared__ __nv_bfloat16 fm_smem[];

__device__ __forceinline__ void split_store(__nv_bfloat16* sH, __nv_bfloat16* sL,
                                            int idx, const float* v) {
#pragma unroll
    for (int j = 0; j < 2; j++) {
        const __nv_bfloat16 h0b = __float2bfloat16(v[j * 2 + 0]);
        const __nv_bfloat16 h1b = __float2bfloat16(v[j * 2 + 1]);
        *reinterpret_cast<__nv_bfloat162*>(sH + idx + j * 2) = __halves2bfloat162(h0b, h1b);
        *reinterpret_cast<__nv_bfloat162*>(sL + idx + j * 2) =
            __halves2bfloat162(__float2bfloat16(v[j * 2 + 0] - __bfloat162float(h0b)),
                               __float2bfloat16(v[j * 2 + 1] - __bfloat162float(h1b)));
    }
}

__device__ __forceinline__ void build_x_both(__nv_bfloat16* sA1h, __nv_bfloat16* sA1l,
                                             __nv_bfloat16* sA2h, __nv_bfloat16* sA2l,
                                             const float* __restrict__ ego,
                                             const float* __restrict__ h0,
                                             int row0, int tid) {
#pragma unroll
    for (int i = tid; i < 128 * 32; i += FM_THREADS) {
        const int r  = i >> 5;
        const int c4 = i & 31;
        const int grow = row0 + r;
        float v1[4] = {0.f, 0.f, 0.f, 0.f};
        float v2[4] = {0.f, 0.f, 0.f, 0.f};
        if (grow < N_NODES) {
            const float4 e = __ldg(reinterpret_cast<const float4*>(ego + (size_t)grow * DIM) + c4);
            const uint2  sp = *(reinterpret_cast<const uint2*>(g_sidebf + (size_t)grow * DIM) + c4);
            const float4 h = __ldg(reinterpret_cast<const float4*>(h0 + (size_t)grow * DIM) + c4);
            const float2 s0 = u32_to_f2(sp.x);
            const float2 s1 = u32_to_f2(sp.y);
            const float oa = 1.0f - ALPHA_C;
            v1[0] = oa * (e.x + s0.x) + ALPHA_C * h.x;
            v1[1] = oa * (e.y + s0.y) + ALPHA_C * h.y;
            v1[2] = oa * (e.z + s1.x) + ALPHA_C * h.z;
            v1[3] = oa * (e.w + s1.y) + ALPHA_C * h.w;
            v2[0] = oa * (e.x * s0.x) + ALPHA_C * h.x;
            v2[1] = oa * (e.y * s0.y) + ALPHA_C * h.y;
            v2[2] = oa * (e.z * s1.x) + ALPHA_C * h.z;
            v2[3] = oa * (e.w * s1.y) + ALPHA_C * h.w;
        }
        const int idx = r * TSTRIDE + c4 * 4;
        split_store(sA1h, sA1l, idx, v1);
        split_store(sA2h, sA2l, idx, v2);
    }
}

__device__ __forceinline__ void run_branch(uint32_t aH, uint32_t aL,
                                           uint32_t bH, uint32_t bL,
                                           float* acc) {
#pragma unroll
    for (int i = 0; i < 32; i++) acc[i] = 0.f;
    for (int ks = 0; ks < 8; ks++) {
        const uint32_t ko = (uint32_t)ks * 32;   // 16 k-elems * 2B
        uint32_t ah[4], al[4];
        ldmat_x4(ah, aH + ko);
        ldmat_x4(al, aL + ko);
#pragma unroll
        for (int np = 0; np < 4; np++) {
            uint32_t bh[4], bl[4];
            const uint32_t bo = (uint32_t)np * (16 * TSTRIDE * 2) + ko;
            ldmat_x4(bh, bH + bo);
            ldmat_x4(bl, bL + bo);
            float* a0 = acc + np * 8;
            mma_bf16(a0,     ah, bh);
            mma_bf16(a0 + 4, ah, bh + 2);
            mma_bf16(a0,     al, bh);
            mma_bf16(a0 + 4, al, bh + 2);
            mma_bf16(a0,     ah, bl);
            mma_bf16(a0 + 4, ah, bl + 2);
        }
    }
}

__global__ __launch_bounds__(FM_THREADS, 1)
void fused_mma_kernel(int row_base,
                      const float* __restrict__ ego,
                      const float* __restrict__ h0,
                      const float* __restrict__ b1,
                      const float* __restrict__ b2,
                      float* __restrict__ out) {
    __shared__ float sb1[DIM], sb2[DIM];

    __nv_bfloat16* sA1h = fm_smem;
    __nv_bfloat16* sA1l = sA1h + TILE_ELEMS;
    __nv_bfloat16* sA2h = sA1l + TILE_ELEMS;
    __nv_bfloat16* sA2l = sA2h + TILE_ELEMS;
    __nv_bfloat16* sBh  = sA2l + TILE_ELEMS;   // one B pair (hi,lo contiguous)

    const int tid  = threadIdx.x;
    const int lane = tid & 31;
    const int w    = tid >> 5;          // 0..15
    const int wr   = w & 7;             // row-group (16 rows)
    const int wn   = w >> 3;            // n-half (64 cols)
    const int row0 = row_base + blockIdx.x * 128;

    if (tid < DIM) { sb1[tid] = b1[tid]; sb2[tid] = b2[tid]; }

    // Copy B1 pair (images 0,1)
    {
        const uint4* g = reinterpret_cast<const uint4*>(g_Bpack);
        uint4* d = reinterpret_cast<uint4*>(sBh);
#pragma unroll
        for (int i = tid; i < 2 * TILE_BYTES / 16; i += FM_THREADS) d[i] = __ldg(g + i);
    }

    // Build both X tiles in one pass
    build_x_both(sA1h, sA1l, sA2h, sA2l, ego, h0, row0, tid);
    __syncthreads();

    // Per-thread ldmatrix base addresses
    const uint32_t aRowByte = (uint32_t)((wr * 16 + (lane & 15)) * (TSTRIDE * 2) + ((lane >> 4) & 1) * 16);
    const uint32_t bRowByte = (uint32_t)((wn * 64 + (lane & 7) + ((lane >> 4) << 3)) * (TSTRIDE * 2) + ((lane >> 3) & 1) * 16);
    const uint32_t a1H = smem_u32(sA1h) + aRowByte;
    const uint32_t a1L = a1H + TILE_BYTES;
    const uint32_t a2H = a1H + 2 * TILE_BYTES;
    const uint32_t a2L = a1H + 3 * TILE_BYTES;
    const uint32_t bH  = smem_u32(sBh) + bRowByte;
    const uint32_t bL  = bH + TILE_BYTES;

    float acc[32], r1[32];

    // Branch 1
    run_branch(a1H, a1L, bH, bL, acc);
    {
        const int c0 = wn * 64 + (lane & 3) * 2;
#pragma unroll
        for (int nt = 0; nt < 8; nt++) {
            const int c = nt * 8 + c0;
            const float bb0 = sb1[c], bbv = sb1[c + 1];
            r1[nt * 4 + 0] = lrelu(acc[nt * 4 + 0] + bb0);
            r1[nt * 4 + 1] = lrelu(acc[nt * 4 + 1] + bbv);
            r1[nt * 4 + 2] = lrelu(acc[nt * 4 + 2] + bb0);
            r1[nt * 4 + 3] = lrelu(acc[nt * 4 + 3] + bbv);
        }
    }
    __syncthreads();               // all warps done reading B1

    // Swap in B2 pair (images 2,3)
    {
        const uint4* g = reinterpret_cast<const uint4*>(g_Bpack) + 2 * TILE_BYTES / 16;
        uint4* d = reinterpret_cast<uint4*>(sBh);
#pragma unroll
        for (int i = tid; i < 2 * TILE_BYTES / 16; i += FM_THREADS) d[i] = __ldg(g + i);
    }
    __syncthreads();

    // Branch 2 (X2 already in smem)
    run_branch(a2H, a2L, bH, bL, acc);

    // Epilogue
    {
        const int c0 = wn * 64 + (lane & 3) * 2;
        const int rlow  = row0 + wr * 16 + (lane >> 2);
        const int rhigh = rlow + 8;
#pragma unroll
        for (int nt = 0; nt < 8; nt++) {
            const int c = nt * 8 + c0;
            const float bb0 = sb2[c], bbv = sb2[c + 1];
            if (rlow < N_NODES) {
                float2 o;
                o.x = r1[nt * 4 + 0] + lrelu(acc[nt * 4 + 0] + bb0);
                o.y = r1[nt * 4 + 1] + lrelu(acc[nt * 4 + 1] + bbv);
                *reinterpret_cast<float2*>(out + (size_t)rlow * DIM + c) = o;
            }
            if (rhigh < N_NODES) {
                float2 o;
                o.x = r1[nt * 4 + 2] + lrelu(acc[nt * 4 + 2] + bb0);
                o.y = r1[nt * 4 + 3] + lrelu(acc[nt * 4 + 3] + bbv);
                *reinterpret_cast<float2*>(out + (size_t)rhigh * DIM + c) = o;
            }
        }
    }
}

// ---------------------------------------------------------------------------
// Launch  [R12 schedule, byte-for-byte]
// Inputs: 0=ego 1=h0 2=vals 3=weight 4=w1 5=b1 6=w2 7=b2 8=row 9=col
// ---------------------------------------------------------------------------
extern "C" void kernel_launch(void* const* d_in, const int* in_sizes, int n_in,
                              void* d_out, int out_size) {
    const float* ego    = (const float*)d_in[0];
    const float* h0     = (const float*)d_in[1];
    const float* vals   = (const float*)d_in[2];
    const float* weight = (const float*)d_in[3];
    const float* w1     = (const float*)d_in[4];
    const float* b1     = (const float*)d_in[5];
    const float* w2     = (const float*)d_in[6];
    const float* b2     = (const float*)d_in[7];
    const int*   row    = (const int*)d_in[8];
    const int*   col    = (const int*)d_in[9];
    float* out = (float*)d_out;

    const int E = in_sizes[2];
    const int smem_bytes = 6 * TILE_BYTES;   // 208896
    cudaFuncSetAttribute(fused_mma_kernel, cudaFuncAttributeMaxDynamicSharedMemorySize, smem_bytes);

    const bool par = g_hx.ok;
    cudaStream_t s0 = 0;
    cudaStream_t s2 = par ? g_hx.s2 : (cudaStream_t)0;
    const int wpb = 8;

    if (par) {
        cudaEventRecord(g_hx.evStart, s0);
        cudaStreamWaitEvent(s2, g_hx.evStart, 0);
        // side stream: fold + pack weights
        compute_M_kernel<<<DIM, DIM, 0, s2>>>(weight, w1, w2);
        cudaEventRecord(g_hx.evM, s2);
    } else {
        compute_M_kernel<<<DIM, DIM>>>(weight, w1, w2);
    }

    // main stream: prep + CSR
    {
        const int total = N_NODES * DIM / 8;
        ego_bf16_kernel<<<(total + 255) / 256, 256, 0, s0>>>(ego);
    }
    hist_kernel<<<1184, 256, 0, s0>>>(row, E);
    scan1_kernel<<<NB_SCAN, SCAN_B, 0, s0>>>();
    scan2_kernel<<<1, 128, 0, s0>>>();
    scan3_kernel<<<(N_NODES + 255) / 256, 256, 0, s0>>>();
    scatter_kernel<<<1184, 256, 0, s0>>>(row, col, vals, E);

    if (par) {
        cudaEventRecord(g_hx.evFork, s0);
        cudaStreamWaitEvent(s2, g_hx.evFork, 0);
        // chunk A on s0, chunk B on s2
        gather_spmm_kernel<<<(NHALF + wpb - 1) / wpb, wpb * 32, 0, s0>>>(0, NHALF);
        gather_spmm_kernel<<<(N_NODES - NHALF + wpb - 1) / wpb, wpb * 32, 0, s2>>>(NHALF, N_NODES);
        // fused on s0 needs Bpack from s2's compute_M
        cudaStreamWaitEvent(s0, g_hx.evM, 0);
        fused_mma_kernel<<<NHALF / 128, FM_THREADS, smem_bytes, s0>>>(0, ego, h0, b1, b2, out);
        fused_mma_kernel<<<(N_NODES - NHALF + 127) / 128, FM_THREADS, smem_bytes, s2>>>(NHALF, ego, h0, b1, b2, out);
        cudaEventRecord(g_hx.evJoin, s2);
        cudaStreamWaitEvent(s0, g_hx.evJoin, 0);
    } else {
        gather_spmm_kernel<<<(N_NODES + wpb - 1) / wpb, wpb * 32, 0, s0>>>(0, N_NODES);
        fused_mma_kernel<<<(N_NODES + 127) / 128, FM_THREADS, smem_bytes>>>(0, ego, h0, b1, b2, out);
    }
}

// round 17
// speedup vs baseline: 1.4185x; 1.0571x over previous
#include <cuda_runtime.h>
#include <cuda_bf16.h>
#include <cstdint>

#define N_NODES 100000
#define DIM     128
#define ALPHA_C 0.1f
#define BETA_C  0.4054651081081644f   // ln(1.5)
#define EMAX    3200000
#define SCAN_B  1024
#define NB_SCAN ((N_NODES + SCAN_B - 1) / SCAN_B)   // 98
#define NHALF   50048                               // 391 * 128

// Padded bf16 tile layout: row stride 136 elements (272 bytes, 16B-aligned,
// conflict-free for ldmatrix)
#define TSTRIDE 136
#define TILE_ELEMS (DIM * TSTRIDE)          // 17408 bf16 per image
#define TILE_BYTES (TILE_ELEMS * 2)         // 34816 B

// ---------------------------------------------------------------------------
// Device scratch (allocation is forbidden)
// ---------------------------------------------------------------------------
__device__ __align__(256) __nv_bfloat16 g_sidebf[(size_t)N_NODES * DIM];
__device__ __align__(256) __nv_bfloat16 g_egobf[(size_t)N_NODES * DIM];
__device__ __align__(256) int   g_cnt[N_NODES];
__device__ __align__(256) int   g_scan[N_NODES];
__device__ __align__(256) int   g_start[N_NODES];
__device__ __align__(256) int   g_cursor[N_NODES];
__device__ __align__(256) int   g_bsum[SCAN_B];
__device__ __align__(256) int   g_boff[SCAN_B];
__device__ __align__(256) int2  g_edge[EMAX];    // interleaved (col, val-bits)
// Packed B images: [0]=B1h [1]=B1l [2]=B2h [3]=B2l, each [n][k] stride TSTRIDE
__device__ __align__(256) __nv_bfloat16 g_Bpack[4 * TILE_ELEMS];

// ---------------------------------------------------------------------------
// Host-side streams/events, created once at static-init (host objects).
// ---------------------------------------------------------------------------
struct HxStreams {
    cudaStream_t s2 = nullptr;
    cudaEvent_t evStart = nullptr, evM = nullptr, evFork = nullptr, evJoin = nullptr;
    bool ok = false;
    HxStreams() {
        if (cudaStreamCreateWithFlags(&s2, cudaStreamNonBlocking) != cudaSuccess) return;
        if (cudaEventCreateWithFlags(&evStart, cudaEventDisableTiming) != cudaSuccess) return;
        if (cudaEventCreateWithFlags(&evM,     cudaEventDisableTiming) != cudaSuccess) return;
        if (cudaEventCreateWithFlags(&evFork,  cudaEventDisableTiming) != cudaSuccess) return;
        if (cudaEventCreateWithFlags(&evJoin,  cudaEventDisableTiming) != cudaSuccess) return;
        ok = true;
    }
};
static HxStreams g_hx;

// ---------------------------------------------------------------------------
// bit-cast helpers (bf16x2 <-> uint32)
// ---------------------------------------------------------------------------
__device__ __forceinline__ uint32_t bf2_to_u32(__nv_bfloat162 v) {
    __nv_bfloat162_raw r = v;
    return (uint32_t)r.x | ((uint32_t)r.y << 16);
}
__device__ __forceinline__ float2 u32_to_f2(uint32_t u) {
    __nv_bfloat162_raw r;
    r.x = (unsigned short)(u & 0xFFFFu);
    r.y = (unsigned short)(u >> 16);
    return __bfloat1622float2(__nv_bfloat162(r));
}

// ---------------------------------------------------------------------------
// PTX helpers: ldmatrix + bf16 mma (target-portable on compute_103)
// ---------------------------------------------------------------------------
__device__ __forceinline__ uint32_t smem_u32(const void* p) {
    uint32_t a;
    asm("{ .reg .u64 t; cvta.to.shared.u64 t, %1; cvt.u32.u64 %0, t; }" : "=r"(a) : "l"(p));
    return a;
}
__device__ __forceinline__ void ldmat_x4(uint32_t* r, uint32_t addr) {
    asm volatile("ldmatrix.sync.aligned.m8n8.x4.shared.b16 {%0,%1,%2,%3}, [%4];"
                 : "=r"(r[0]), "=r"(r[1]), "=r"(r[2]), "=r"(r[3]) : "r"(addr));
}
__device__ __forceinline__ void mma_bf16(float* d, const uint32_t* a, const uint32_t* b) {
    asm volatile(
        "mma.sync.aligned.m16n8k16.row.col.f32.bf16.bf16.f32 "
        "{%0,%1,%2,%3},{%4,%5,%6,%7},{%8,%9},{%0,%1,%2,%3};"
        : "+f"(d[0]), "+f"(d[1]), "+f"(d[2]), "+f"(d[3])
        : "r"(a[0]), "r"(a[1]), "r"(a[2]), "r"(a[3]), "r"(b[0]), "r"(b[1]));
}

__device__ __forceinline__ float lrelu(float x) { return fmaxf(x, 0.01f * x); }

// ---------------------------------------------------------------------------
// compute_M: M1 = im@w1, M2 = im@w2 (im = (1-beta)+beta*weight); store
// transposed hi/lo bf16 into padded [n][k] images.
// ---------------------------------------------------------------------------
__global__ void compute_M_kernel(const float* __restrict__ weight,
                                 const float* __restrict__ w1,
                                 const float* __restrict__ w2) {
    __shared__ float sIm[DIM];
    const int i = blockIdx.x;   // k
    const int j = threadIdx.x;  // n
    sIm[j] = (1.0f - BETA_C) + BETA_C * weight[i * DIM + j];
    __syncthreads();
    float a1 = 0.0f, a2 = 0.0f;
#pragma unroll 8
    for (int k = 0; k < DIM; k++) {
        const float im = sIm[k];
        a1 = fmaf(im, __ldg(w1 + k * DIM + j), a1);
        a2 = fmaf(im, __ldg(w2 + k * DIM + j), a2);
    }
    const __nv_bfloat16 h1 = __float2bfloat16(a1);
    const __nv_bfloat16 l1 = __float2bfloat16(a1 - __bfloat162float(h1));
    const __nv_bfloat16 h2 = __float2bfloat16(a2);
    const __nv_bfloat16 l2 = __float2bfloat16(a2 - __bfloat162float(h2));
    const int base = j * TSTRIDE + i;    // [n][k]
    g_Bpack[0 * TILE_ELEMS + base] = h1;
    g_Bpack[1 * TILE_ELEMS + base] = l1;
    g_Bpack[2 * TILE_ELEMS + base] = h2;
    g_Bpack[3 * TILE_ELEMS + base] = l2;
}

// ---------------------------------------------------------------------------
// ego -> bf16 copy + zero counts (fused)
// ---------------------------------------------------------------------------
__global__ void ego_bf16_kernel(const float* __restrict__ ego) {
    const int idx = blockIdx.x * blockDim.x + threadIdx.x;   // one per 8 elems
    const int total = N_NODES * DIM / 8;
    if (idx < N_NODES) g_cnt[idx] = 0;
    if (idx >= total) return;
    const float4 a = __ldg(reinterpret_cast<const float4*>(ego) + idx * 2);
    const float4 b = __ldg(reinterpret_cast<const float4*>(ego) + idx * 2 + 1);
    uint4 o;
    o.x = bf2_to_u32(__floats2bfloat162_rn(a.x, a.y));
    o.y = bf2_to_u32(__floats2bfloat162_rn(a.z, a.w));
    o.z = bf2_to_u32(__floats2bfloat162_rn(b.x, b.y));
    o.w = bf2_to_u32(__floats2bfloat162_rn(b.z, b.w));
    reinterpret_cast<uint4*>(g_egobf)[idx] = o;
}

// ---------------------------------------------------------------------------
// CSR build (hist/scatter vectorized, grid-stride)
// ---------------------------------------------------------------------------
__global__ void hist_kernel(const int* __restrict__ row, int E) {
    const int tid = blockIdx.x * blockDim.x + threadIdx.x;
    const int stride = gridDim.x * blockDim.x;
    const int n4 = E >> 2;
    for (int i = tid; i < n4; i += stride) {
        const int4 r = __ldg(reinterpret_cast<const int4*>(row) + i);
        atomicAdd(&g_cnt[r.x], 1);
        atomicAdd(&g_cnt[r.y], 1);
        atomicAdd(&g_cnt[r.z], 1);
        atomicAdd(&g_cnt[r.w], 1);
    }
    if (tid < (E & 3)) atomicAdd(&g_cnt[__ldg(row + (n4 << 2) + tid)], 1);
}
__global__ void scan1_kernel() {
    __shared__ int s[SCAN_B];
    const int tid = threadIdx.x;
    const int i = blockIdx.x * SCAN_B + tid;
    int v = (i < N_NODES) ? g_cnt[i] : 0;
    s[tid] = v;
    __syncthreads();
#pragma unroll
    for (int off = 1; off < SCAN_B; off <<= 1) {
        int t = (tid >= off) ? s[tid - off] : 0;
        __syncthreads();
        s[tid] += t;
        __syncthreads();
    }
    if (i < N_NODES) g_scan[i] = s[tid];
    if (tid == SCAN_B - 1) g_bsum[blockIdx.x] = s[tid];
}
__global__ void scan2_kernel() {
    __shared__ int s[128];
    const int tid = threadIdx.x;
    int v = (tid < NB_SCAN) ? g_bsum[tid] : 0;
    s[tid] = v;
    __syncthreads();
#pragma unroll
    for (int off = 1; off < 128; off <<= 1) {
        int t = (tid >= off) ? s[tid - off] : 0;
        __syncthreads();
        s[tid] += t;
        __syncthreads();
    }
    if (tid < NB_SCAN) g_boff[tid] = s[tid] - v;
}
__global__ void scan3_kernel() {
    const int i = blockIdx.x * blockDim.x + threadIdx.x;
    if (i < N_NODES) {
        const int excl = g_scan[i] - g_cnt[i] + g_boff[i / SCAN_B];
        g_start[i]  = excl;
        g_cursor[i] = excl;
    }
}
__global__ void scatter_kernel(const int* __restrict__ row,
                               const int* __restrict__ col,
                               const float* __restrict__ vals, int E) {
    const int tid = blockIdx.x * blockDim.x + threadIdx.x;
    const int stride = gridDim.x * blockDim.x;
    const int n4 = E >> 2;
    for (int i = tid; i < n4; i += stride) {
        const int4   r = __ldg(reinterpret_cast<const int4*>(row) + i);
        const int4   c = __ldg(reinterpret_cast<const int4*>(col) + i);
        const float4 v = __ldg(reinterpret_cast<const float4*>(vals) + i);
        int p0 = atomicAdd(&g_cursor[r.x], 1);
        int p1 = atomicAdd(&g_cursor[r.y], 1);
        int p2 = atomicAdd(&g_cursor[r.z], 1);
        int p3 = atomicAdd(&g_cursor[r.w], 1);
        g_edge[p0] = make_int2(c.x, __float_as_int(v.x));
        g_edge[p1] = make_int2(c.y, __float_as_int(v.y));
        g_edge[p2] = make_int2(c.z, __float_as_int(v.z));
        g_edge[p3] = make_int2(c.w, __float_as_int(v.w));
    }
    if (tid < (E & 3)) {
        const int e = (n4 << 2) + tid;
        const int r = __ldg(row + e);
        const int pos = atomicAdd(&g_cursor[r], 1);
        g_edge[pos] = make_int2(__ldg(col + e), __float_as_int(__ldg(vals + e)));
    }
}

// ---------------------------------------------------------------------------
// Gather SpMM: 16 lanes per edge-row (uint4 loads), half-warp processes 2
// edges per step. Halves LDG + SHFL instruction counts vs uint2 scheme.
// Row range [base, limit). Writes side in bf16 (uint4 per lane<16).
// ---------------------------------------------------------------------------
__device__ __forceinline__ void acc_edge8(float* acc, float v, uint4 p) {
    const float2 f0 = u32_to_f2(p.x);
    const float2 f1 = u32_to_f2(p.y);
    const float2 f2 = u32_to_f2(p.z);
    const float2 f3 = u32_to_f2(p.w);
    acc[0] = fmaf(v, f0.x, acc[0]); acc[1] = fmaf(v, f0.y, acc[1]);
    acc[2] = fmaf(v, f1.x, acc[2]); acc[3] = fmaf(v, f1.y, acc[3]);
    acc[4] = fmaf(v, f2.x, acc[4]); acc[5] = fmaf(v, f2.y, acc[5]);
    acc[6] = fmaf(v, f3.x, acc[6]); acc[7] = fmaf(v, f3.y, acc[7]);
}

__global__ __launch_bounds__(256)
void gather_spmm_kernel(int base, int limit) {
    const int wid  = base + ((blockIdx.x * blockDim.x + threadIdx.x) >> 5);
    const int lane = threadIdx.x & 31;
    if (wid >= limit) return;
    const int half = lane >> 4;    // which edge of the pair
    const int sub  = lane & 15;    // col group: elems [sub*8, sub*8+8)

    const int start = g_start[wid];
    const int cnt   = g_cnt[wid];

    float acc[8];
#pragma unroll
    for (int i = 0; i < 8; i++) acc[i] = 0.f;

    for (int j0 = 0; j0 < cnt; j0 += 32) {
        const int rem = min(32, cnt - j0);
        int   myc = 0;
        float myv = 0.f;
        if (lane < rem) {
            const int2 ed = __ldg(g_edge + start + j0 + lane);
            myc = ed.x;
            myv = __int_as_float(ed.y);
        }
        int kk = 0;
        // 8 edges per unrolled block: 4 pair-steps, 4 x LDG.128 in flight
        for (; kk + 8 <= rem; kk += 8) {
            int   c[4];
            float v[4];
            uint4 p[4];
#pragma unroll
            for (int q = 0; q < 4; q++) {
                const int src = kk + q * 2 + half;
                c[q] = __shfl_sync(0xffffffffu, myc, src);
                v[q] = __shfl_sync(0xffffffffu, myv, src);
            }
#pragma unroll
            for (int q = 0; q < 4; q++)
                p[q] = __ldg(reinterpret_cast<const uint4*>(g_egobf + (size_t)c[q] * DIM) + sub);
#pragma unroll
            for (int q = 0; q < 4; q++) acc_edge8(acc, v[q], p[q]);
        }
        // remainder pairs (invalid lane-edges have myv=0 -> harmless)
        for (; kk < rem; kk += 2) {
            const int src = kk + half;                 // < 32 always here
            const int   c = __shfl_sync(0xffffffffu, myc, src);
            const float v = __shfl_sync(0xffffffffu, myv, src);
            const uint4 p = __ldg(reinterpret_cast<const uint4*>(g_egobf + (size_t)c * DIM) + sub);
            acc_edge8(acc, v, p);
        }
    }

    // combine the two half-warp partials (same cols, disjoint edges)
#pragma unroll
    for (int i = 0; i < 8; i++)
        acc[i] += __shfl_xor_sync(0xffffffffu, acc[i], 16);

    if (half == 0) {
        uint4 o;
        o.x = bf2_to_u32(__floats2bfloat162_rn(acc[0], acc[1]));
        o.y = bf2_to_u32(__floats2bfloat162_rn(acc[2], acc[3]));
        o.z = bf2_to_u32(__floats2bfloat162_rn(acc[4], acc[5]));
        o.w = bf2_to_u32(__floats2bfloat162_rn(acc[6], acc[7]));
        reinterpret_cast<uint4*>(g_sidebf + (size_t)wid * DIM)[sub] = o;
    }
}

// ---------------------------------------------------------------------------
// Fused dense via mma.sync (bf16x3 split == ~fp32), 512 threads / CTA.
// Single-pass X build (side read in bf16); B1 then B2 through one smem slot.
// ---------------------------------------------------------------------------
#define FM_THREADS 512

extern __shared__ __nv_bfloat16 fm_smem[];

__device__ __forceinline__ void split_store(__nv_bfloat16* sH, __nv_bfloat16* sL,
                                            int idx, const float* v) {
#pragma unroll
    for (int j = 0; j < 2; j++) {
        const __nv_bfloat16 h0b = __float2bfloat16(v[j * 2 + 0]);
        const __nv_bfloat16 h1b = __float2bfloat16(v[j * 2 + 1]);
        *reinterpret_cast<__nv_bfloat162*>(sH + idx + j * 2) = __halves2bfloat162(h0b, h1b);
        *reinterpret_cast<__nv_bfloat162*>(sL + idx + j * 2) =
            __halves2bfloat162(__float2bfloat16(v[j * 2 + 0] - __bfloat162float(h0b)),
                               __float2bfloat16(v[j * 2 + 1] - __bfloat162float(h1b)));
    }
}

__device__ __forceinline__ void build_x_both(__nv_bfloat16* sA1h, __nv_bfloat16* sA1l,
                                             __nv_bfloat16* sA2h, __nv_bfloat16* sA2l,
                                             const float* __restrict__ ego,
                                             const float* __restrict__ h0,
                                             int row0, int tid) {
#pragma unroll
    for (int i = tid; i < 128 * 32; i += FM_THREADS) {
        const int r  = i >> 5;
        const int c4 = i & 31;
        const int grow = row0 + r;
        float v1[4] = {0.f, 0.f, 0.f, 0.f};
        float v2[4] = {0.f, 0.f, 0.f, 0.f};
        if (grow < N_NODES) {
            const float4 e = __ldg(reinterpret_cast<const float4*>(ego + (size_t)grow * DIM) + c4);
            const uint2  sp = *(reinterpret_cast<const uint2*>(g_sidebf + (size_t)grow * DIM) + c4);
            const float4 h = __ldg(reinterpret_cast<const float4*>(h0 + (size_t)grow * DIM) + c4);
            const float2 s0 = u32_to_f2(sp.x);
            const float2 s1 = u32_to_f2(sp.y);
            const float oa = 1.0f - ALPHA_C;
            v1[0] = oa * (e.x + s0.x) + ALPHA_C * h.x;
            v1[1] = oa * (e.y + s0.y) + ALPHA_C * h.y;
            v1[2] = oa * (e.z + s1.x) + ALPHA_C * h.z;
            v1[3] = oa * (e.w + s1.y) + ALPHA_C * h.w;
            v2[0] = oa * (e.x * s0.x) + ALPHA_C * h.x;
            v2[1] = oa * (e.y * s0.y) + ALPHA_C * h.y;
            v2[2] = oa * (e.z * s1.x) + ALPHA_C * h.z;
            v2[3] = oa * (e.w * s1.y) + ALPHA_C * h.w;
        }
        const int idx = r * TSTRIDE + c4 * 4;
        split_store(sA1h, sA1l, idx, v1);
        split_store(sA2h, sA2l, idx, v2);
    }
}

__device__ __forceinline__ void run_branch(uint32_t aH, uint32_t aL,
                                           uint32_t bH, uint32_t bL,
                                           float* acc) {
#pragma unroll
    for (int i = 0; i < 32; i++) acc[i] = 0.f;
    for (int ks = 0; ks < 8; ks++) {
        const uint32_t ko = (uint32_t)ks * 32;   // 16 k-elems * 2B
        uint32_t ah[4], al[4];
        ldmat_x4(ah, aH + ko);
        ldmat_x4(al, aL + ko);
#pragma unroll
        for (int np = 0; np < 4; np++) {
            uint32_t bh[4], bl[4];
            const uint32_t bo = (uint32_t)np * (16 * TSTRIDE * 2) + ko;
            ldmat_x4(bh, bH + bo);
            ldmat_x4(bl, bL + bo);
            float* a0 = acc + np * 8;
            mma_bf16(a0,     ah, bh);
            mma_bf16(a0 + 4, ah, bh + 2);
            mma_bf16(a0,     al, bh);
            mma_bf16(a0 + 4, al, bh + 2);
            mma_bf16(a0,     ah, bl);
            mma_bf16(a0 + 4, ah, bl + 2);
        }
    }
}

__global__ __launch_bounds__(FM_THREADS, 1)
void fused_mma_kernel(int row_base,
                      const float* __restrict__ ego,
                      const float* __restrict__ h0,
                      const float* __restrict__ b1,
                      const float* __restrict__ b2,
                      float* __restrict__ out) {
    __shared__ float sb1[DIM], sb2[DIM];

    __nv_bfloat16* sA1h = fm_smem;
    __nv_bfloat16* sA1l = sA1h + TILE_ELEMS;
    __nv_bfloat16* sA2h = sA1l + TILE_ELEMS;
    __nv_bfloat16* sA2l = sA2h + TILE_ELEMS;
    __nv_bfloat16* sBh  = sA2l + TILE_ELEMS;   // one B pair (hi,lo contiguous)

    const int tid  = threadIdx.x;
    const int lane = tid & 31;
    const int w    = tid >> 5;          // 0..15
    const int wr   = w & 7;             // row-group (16 rows)
    const int wn   = w >> 3;            // n-half (64 cols)
    const int row0 = row_base + blockIdx.x * 128;

    if (tid < DIM) { sb1[tid] = b1[tid]; sb2[tid] = b2[tid]; }

    // Copy B1 pair (images 0,1)
    {
        const uint4* g = reinterpret_cast<const uint4*>(g_Bpack);
        uint4* d = reinterpret_cast<uint4*>(sBh);
#pragma unroll
        for (int i = tid; i < 2 * TILE_BYTES / 16; i += FM_THREADS) d[i] = __ldg(g + i);
    }

    // Build both X tiles in one pass
    build_x_both(sA1h, sA1l, sA2h, sA2l, ego, h0, row0, tid);
    __syncthreads();

    // Per-thread ldmatrix base addresses
    const uint32_t aRowByte = (uint32_t)((wr * 16 + (lane & 15)) * (TSTRIDE * 2) + ((lane >> 4) & 1) * 16);
    const uint32_t bRowByte = (uint32_t)((wn * 64 + (lane & 7) + ((lane >> 4) << 3)) * (TSTRIDE * 2) + ((lane >> 3) & 1) * 16);
    const uint32_t a1H = smem_u32(sA1h) + aRowByte;
    const uint32_t a1L = a1H + TILE_BYTES;
    const uint32_t a2H = a1H + 2 * TILE_BYTES;
    const uint32_t a2L = a1H + 3 * TILE_BYTES;
    const uint32_t bH  = smem_u32(sBh) + bRowByte;
    const uint32_t bL  = bH + TILE_BYTES;

    float acc[32], r1[32];

    // Branch 1
    run_branch(a1H, a1L, bH, bL, acc);
    {
        const int c0 = wn * 64 + (lane & 3) * 2;
#pragma unroll
        for (int nt = 0; nt < 8; nt++) {
            const int c = nt * 8 + c0;
            const float bb0 = sb1[c], bbv = sb1[c + 1];
            r1[nt * 4 + 0] = lrelu(acc[nt * 4 + 0] + bb0);
            r1[nt * 4 + 1] = lrelu(acc[nt * 4 + 1] + bbv);
            r1[nt * 4 + 2] = lrelu(acc[nt * 4 + 2] + bb0);
            r1[nt * 4 + 3] = lrelu(acc[nt * 4 + 3] + bbv);
        }
    }
    __syncthreads();               // all warps done reading B1

    // Swap in B2 pair (images 2,3)
    {
        const uint4* g = reinterpret_cast<const uint4*>(g_Bpack) + 2 * TILE_BYTES / 16;
        uint4* d = reinterpret_cast<uint4*>(sBh);
#pragma unroll
        for (int i = tid; i < 2 * TILE_BYTES / 16; i += FM_THREADS) d[i] = __ldg(g + i);
    }
    __syncthreads();

    // Branch 2 (X2 already in smem)
    run_branch(a2H, a2L, bH, bL, acc);

    // Epilogue
    {
        const int c0 = wn * 64 + (lane & 3) * 2;
        const int rlow  = row0 + wr * 16 + (lane >> 2);
        const int rhigh = rlow + 8;
#pragma unroll
        for (int nt = 0; nt < 8; nt++) {
            const int c = nt * 8 + c0;
            const float bb0 = sb2[c], bbv = sb2[c + 1];
            if (rlow < N_NODES) {
                float2 o;
                o.x = r1[nt * 4 + 0] + lrelu(acc[nt * 4 + 0] + bb0);
                o.y = r1[nt * 4 + 1] + lrelu(acc[nt * 4 + 1] + bbv);
                *reinterpret_cast<float2*>(out + (size_t)rlow * DIM + c) = o;
            }
            if (rhigh < N_NODES) {
                float2 o;
                o.x = r1[nt * 4 + 2] + lrelu(acc[nt * 4 + 2] + bb0);
                o.y = r1[nt * 4 + 3] + lrelu(acc[nt * 4 + 3] + bbv);
                *reinterpret_cast<float2*>(out + (size_t)rhigh * DIM + c) = o;
            }
        }
    }
}

// ---------------------------------------------------------------------------
// Launch  [R12/R16 schedule, byte-for-byte]
// Inputs: 0=ego 1=h0 2=vals 3=weight 4=w1 5=b1 6=w2 7=b2 8=row 9=col
// ---------------------------------------------------------------------------
extern "C" void kernel_launch(void* const* d_in, const int* in_sizes, int n_in,
                              void* d_out, int out_size) {
    const float* ego    = (const float*)d_in[0];
    const float* h0     = (const float*)d_in[1];
    const float* vals   = (const float*)d_in[2];
    const float* weight = (const float*)d_in[3];
    const float* w1     = (const float*)d_in[4];
    const float* b1     = (const float*)d_in[5];
    const float* w2     = (const float*)d_in[6];
    const float* b2     = (const float*)d_in[7];
    const int*   row    = (const int*)d_in[8];
    const int*   col    = (const int*)d_in[9];
    float* out = (float*)d_out;

    const int E = in_sizes[2];
    const int smem_bytes = 6 * TILE_BYTES;   // 208896
    cudaFuncSetAttribute(fused_mma_kernel, cudaFuncAttributeMaxDynamicSharedMemorySize, smem_bytes);

    const bool par = g_hx.ok;
    cudaStream_t s0 = 0;
    cudaStream_t s2 = par ? g_hx.s2 : (cudaStream_t)0;
    const int wpb = 8;

    if (par) {
        cudaEventRecord(g_hx.evStart, s0);
        cudaStreamWaitEvent(s2, g_hx.evStart, 0);
        // side stream: fold + pack weights
        compute_M_kernel<<<DIM, DIM, 0, s2>>>(weight, w1, w2);
        cudaEventRecord(g_hx.evM, s2);
    } else {
        compute_M_kernel<<<DIM, DIM>>>(weight, w1, w2);
    }

    // main stream: prep + CSR
    {
        const int total = N_NODES * DIM / 8;
        ego_bf16_kernel<<<(total + 255) / 256, 256, 0, s0>>>(ego);
    }
    hist_kernel<<<1184, 256, 0, s0>>>(row, E);
    scan1_kernel<<<NB_SCAN, SCAN_B, 0, s0>>>();
    scan2_kernel<<<1, 128, 0, s0>>>();
    scan3_kernel<<<(N_NODES + 255) / 256, 256, 0, s0>>>();
    scatter_kernel<<<1184, 256, 0, s0>>>(row, col, vals, E);

    if (par) {
        cudaEventRecord(g_hx.evFork, s0);
        cudaStreamWaitEvent(s2, g_hx.evFork, 0);
        // chunk A on s0, chunk B on s2
        gather_spmm_kernel<<<(NHALF + wpb - 1) / wpb, wpb * 32, 0, s0>>>(0, NHALF);
        gather_spmm_kernel<<<(N_NODES - NHALF + wpb - 1) / wpb, wpb * 32, 0, s2>>>(NHALF, N_NODES);
        // fused on s0 needs Bpack from s2's compute_M
        cudaStreamWaitEvent(s0, g_hx.evM, 0);
        fused_mma_kernel<<<NHALF / 128, FM_THREADS, smem_bytes, s0>>>(0, ego, h0, b1, b2, out);
        fused_mma_kernel<<<(N_NODES - NHALF + 127) / 128, FM_THREADS, smem_bytes, s2>>>(NHALF, ego, h0, b1, b2, out);
        cudaEventRecord(g_hx.evJoin, s2);
        cudaStreamWaitEvent(s0, g_hx.evJoin, 0);
    } else {
        gather_spmm_kernel<<<(N_NODES + wpb - 1) / wpb, wpb * 32, 0, s0>>>(0, N_NODES);
        fused_mma_kernel<<<(N_NODES + 127) / 128, FM_THREADS, smem_bytes>>>(0, ego, h0, b1, b2, out);
    }
}